// round 4
// baseline (speedup 1.0000x reference)
#include <cuda_runtime.h>
#include <math.h>

#define T_STEPS 1000
#define BATCH   256
#define IDIM    128
#define NDIM    512
#define ALPHA   0.2f
#define NB      128    // persistent scan blocks (16 n-tiles x 8 b-tiles)

#define NGROUPS 8       // one warp per group, each covers 64 k
#define KSLICE  64
#define RED_STRIDE 36   // 32 + 4 pad

// Shared memory layout (floats):
//   Wl  [512][32]            @ 0       (64 KB)  W_hh slice, resident all steps
//   Hs  [8][32*16 float4]    @ 16384   (64 KB)  per-group staged hprev (swizzled)
//   red [8][32][RED_STRIDE]  @ 32768   (36 KB)  per-group partial sums
#define SMEM_WL   0
#define SMEM_HS   16384
#define SMEM_RED  32768
#define SMEM_FLOATS (SMEM_RED + NGROUPS * 32 * RED_STRIDE)   // 41984

typedef unsigned long long ull;

__device__ __forceinline__ ull pack_dup(float a) {
    ull r;
    asm("mov.b64 %0, {%1, %1};" : "=l"(r) : "r"(__float_as_uint(a)));
    return r;
}
__device__ __forceinline__ void ffma2(ull& d, ull a, ull b) {
    asm("fma.rn.f32x2 %0, %1, %2, %0;" : "+l"(d) : "l"(a), "l"(b));
}
__device__ __forceinline__ float lo_f(ull v) { return __uint_as_float((unsigned)(v & 0xffffffffu)); }
__device__ __forceinline__ float hi_f(ull v) { return __uint_as_float((unsigned)(v >> 32)); }

// ---------------------------------------------------------------------------
// Grid barrier flags (persistent; epoch derived from flag state => replay-safe)
// ---------------------------------------------------------------------------
__device__ unsigned g_flags[NB];

// ---------------------------------------------------------------------------
// Input projection GEMM:  C[M,N] = X[M,K] * W[N,K]^T + b   (f32x2 inner loop)
// M = T*B = 256000, K = 128, N = 512.  Tile 128x128, BK=16, 256 thr, 8x8 micro.
// ---------------------------------------------------------------------------
__global__ __launch_bounds__(256) void gemm_in_kernel(
    const float* __restrict__ X, const float* __restrict__ W,
    const float* __restrict__ bias, float* __restrict__ C)
{
    const int BK = 16;
    __shared__ float As[BK][128 + 4];
    __shared__ float Bs[BK][128 + 4];

    const int tid = threadIdx.x;
    const int tx = tid & 15;   // n group (8 cols each)
    const int ty = tid >> 4;   // m group (8 rows each)
    const int mBase = blockIdx.y * 128;
    const int nBase = blockIdx.x * 128;
    const float* Xblk = X + (size_t)mBase * IDIM;
    const float* Wblk = W + (size_t)nBase * IDIM;

    ull acc[8][4];
#pragma unroll
    for (int i = 0; i < 8; i++)
#pragma unroll
        for (int j = 0; j < 4; j++) acc[i][j] = 0ull;

    for (int kc = 0; kc < IDIM; kc += BK) {
#pragma unroll
        for (int r = 0; r < 2; r++) {
            int f = tid + r * 256;          // [0,512) float4 slots
            int m = f >> 2;                 // row within tile
            int q = f & 3;                  // which float4 of the 16-wide k chunk
            float4 va = *(const float4*)(Xblk + (size_t)m * IDIM + kc + q * 4);
            As[q * 4 + 0][m] = va.x; As[q * 4 + 1][m] = va.y;
            As[q * 4 + 2][m] = va.z; As[q * 4 + 3][m] = va.w;
            float4 vb = *(const float4*)(Wblk + (size_t)m * IDIM + kc + q * 4);
            Bs[q * 4 + 0][m] = vb.x; Bs[q * 4 + 1][m] = vb.y;
            Bs[q * 4 + 2][m] = vb.z; Bs[q * 4 + 3][m] = vb.w;
        }
        __syncthreads();
#pragma unroll
        for (int k = 0; k < BK; k++) {
            float a[8];
            *(float4*)&a[0] = *(const float4*)&As[k][ty * 8];
            *(float4*)&a[4] = *(const float4*)&As[k][ty * 8 + 4];
            ulonglong2 b01 = *(const ulonglong2*)&Bs[k][tx * 8];
            ulonglong2 b23 = *(const ulonglong2*)&Bs[k][tx * 8 + 4];
#pragma unroll
            for (int i = 0; i < 8; i++) {
                ull d = pack_dup(a[i]);
                ffma2(acc[i][0], d, b01.x);
                ffma2(acc[i][1], d, b01.y);
                ffma2(acc[i][2], d, b23.x);
                ffma2(acc[i][3], d, b23.y);
            }
        }
        __syncthreads();
    }

#pragma unroll
    for (int i = 0; i < 8; i++) {
        int m = mBase + ty * 8 + i;
        float* crow = C + (size_t)m * NDIM + nBase + tx * 8;
#pragma unroll
        for (int j = 0; j < 4; j++) {
            crow[2 * j + 0] = lo_f(acc[i][j]) + bias[nBase + tx * 8 + 2 * j + 0];
            crow[2 * j + 1] = hi_f(acc[i][j]) + bias[nBase + tx * 8 + 2 * j + 1];
        }
    }
}

// ---------------------------------------------------------------------------
// Persistent recurrent scan kernel. 128 blocks x 256 threads (8 warps).
//   Block (bi, ni): output tile rows [bi*32,+32) x cols [ni*32,+32).
//   8 warp-groups; group g covers k in [g*64, g*64+64). Micro-tile 4b x 8n,
//   accumulators packed as f32x2 pairs over n. W_hh slice resident in smem.
//   Hs staged with XOR-by-ty swizzle: phys_f4(bl, kq) = bl*16 + (kq ^ (bl>>2)).
// ---------------------------------------------------------------------------
extern __shared__ float s_mem[];

__global__ __launch_bounds__(256, 1) void ctrnn_scan_kernel(
    const float* __restrict__ h0,
    const float* __restrict__ W_hh,
    float* __restrict__ out)
{
    float* Wl = s_mem + SMEM_WL;

    const int tid  = threadIdx.x;
    const int g    = tid >> 5;      // warp-group 0..7
    const int gtid = tid & 31;
    const int tx   = gtid & 3;      // n micro (8 cols)
    const int ty   = gtid >> 2;     // b micro (4 rows), 0..7
    const int kOff = g * KSLICE;

    const int ni = blockIdx.x;      // 0..15
    const int bi = blockIdx.y;      // 0..7
    const int bid = bi * 16 + ni;
    const int nBase = ni * 32;
    const int bBase = bi * 32;

    float* HsG  = s_mem + SMEM_HS  + g * (32 * 64);
    float* redG = s_mem + SMEM_RED + g * (32 * RED_STRIDE);

    // epilogue mapping: one float4 of the 32x32 tile per thread
    const int eb = tid >> 3;
    const int en = tid & 7;

    // Load W_hh[nBase..+32)[0..512) transposed into Wl[k][n_local]. Once.
    for (int f = tid; f < 32 * (NDIM / 4); f += 256) {
        int n = f >> 7;          // local n row
        int q = f & 127;         // float4 along k
        float4 v = *(const float4*)(W_hh + (size_t)(nBase + n) * NDIM + q * 4);
        Wl[(q * 4 + 0) * 32 + n] = v.x; Wl[(q * 4 + 1) * 32 + n] = v.y;
        Wl[(q * 4 + 2) * 32 + n] = v.z; Wl[(q * 4 + 3) * 32 + n] = v.w;
    }

    // Replay-safe epoch base: all flags equal at kernel entry.
    unsigned base = ((volatile unsigned*)g_flags)[bid];
    __syncthreads();

    const float* wBase = Wl + (size_t)kOff * 32 + tx * 8;

    for (int t = 0; t < T_STEPS; t++) {
        const float* hprev = (t == 0) ? h0 : out + (size_t)(t - 1) * BATCH * NDIM;
        float* hcur = out + (size_t)t * BATCH * NDIM;

        // Epilogue operands prefetch (valid after previous barrier).
        const size_t eoff = (size_t)(bBase + eb) * NDIM + nBase + en * 4;
        float4 xp4 = *(const float4*)(hcur + eoff);
        float4 hp4 = __ldcg((const float4*)(hprev + eoff));

        // Stage this group's 64-k slice of hprev, swizzled.
#pragma unroll
        for (int r = 0; r < 16; r++) {
            int f = gtid + r * 32;
            int kq = f & 15;         // float4 within 64-wide slice
            int bl = f >> 4;         // local b row
            float4 v = __ldcg((const float4*)(hprev +
                          (size_t)(bBase + bl) * NDIM + kOff + kq * 4));
            int phys = bl * 16 + (kq ^ (bl >> 2));
            *(float4*)(HsG + phys * 4) = v;
        }
        __syncwarp();

        ull acc[4][4];
#pragma unroll
        for (int i = 0; i < 4; i++)
#pragma unroll
            for (int j = 0; j < 4; j++) acc[i][j] = 0ull;

#pragma unroll 4
        for (int kq = 0; kq < 16; kq++) {
            const int sw = (kq ^ ty) * 4;
            float a0[4], a1[4], a2[4], a3[4];
            *(float4*)a0 = *(const float4*)(HsG + (4 * ty + 0) * 64 + sw);
            *(float4*)a1 = *(const float4*)(HsG + (4 * ty + 1) * 64 + sw);
            *(float4*)a2 = *(const float4*)(HsG + (4 * ty + 2) * 64 + sw);
            *(float4*)a3 = *(const float4*)(HsG + (4 * ty + 3) * 64 + sw);
#pragma unroll
            for (int kk = 0; kk < 4; kk++) {
                const float* wr = wBase + (kq * 4 + kk) * 32;
                ulonglong2 wA = *(const ulonglong2*)wr;
                ulonglong2 wB = *(const ulonglong2*)(wr + 4);
                ull d0 = pack_dup(a0[kk]);
                ffma2(acc[0][0], d0, wA.x); ffma2(acc[0][1], d0, wA.y);
                ffma2(acc[0][2], d0, wB.x); ffma2(acc[0][3], d0, wB.y);
                ull d1 = pack_dup(a1[kk]);
                ffma2(acc[1][0], d1, wA.x); ffma2(acc[1][1], d1, wA.y);
                ffma2(acc[1][2], d1, wB.x); ffma2(acc[1][3], d1, wB.y);
                ull d2 = pack_dup(a2[kk]);
                ffma2(acc[2][0], d2, wA.x); ffma2(acc[2][1], d2, wA.y);
                ffma2(acc[2][2], d2, wB.x); ffma2(acc[2][3], d2, wB.y);
                ull d3 = pack_dup(a3[kk]);
                ffma2(acc[3][0], d3, wA.x); ffma2(acc[3][1], d3, wA.y);
                ffma2(acc[3][2], d3, wB.x); ffma2(acc[3][3], d3, wB.y);
            }
        }

        // Write partials; reduce + epilogue with all 256 threads.
#pragma unroll
        for (int i = 0; i < 4; i++) {
            float* rp = redG + (4 * ty + i) * RED_STRIDE + tx * 8;
            *(float4*)rp = make_float4(lo_f(acc[i][0]), hi_f(acc[i][0]),
                                       lo_f(acc[i][1]), hi_f(acc[i][1]));
            *(float4*)(rp + 4) = make_float4(lo_f(acc[i][2]), hi_f(acc[i][2]),
                                             lo_f(acc[i][3]), hi_f(acc[i][3]));
        }
        __syncthreads();

        {
            float4 s = make_float4(0.f, 0.f, 0.f, 0.f);
#pragma unroll
            for (int gg = 0; gg < NGROUPS; gg++) {
                float4 p = *(const float4*)(s_mem + SMEM_RED
                            + gg * (32 * RED_STRIDE) + eb * RED_STRIDE + en * 4);
                s.x += p.x; s.y += p.y; s.z += p.z; s.w += p.w;
            }
            float4 o;
            o.x = hp4.x * (1.f - ALPHA) + ALPHA * tanhf(xp4.x + s.x);
            o.y = hp4.y * (1.f - ALPHA) + ALPHA * tanhf(xp4.y + s.y);
            o.z = hp4.z * (1.f - ALPHA) + ALPHA * tanhf(xp4.z + s.z);
            o.w = hp4.w * (1.f - ALPHA) + ALPHA * tanhf(xp4.w + s.w);
            *(float4*)(hcur + eoff) = o;
        }

        // ---- barrier among the 16 blocks sharing bi ----
        unsigned epoch = base + (unsigned)t + 1u;
        __threadfence();
        __syncthreads();
        if (tid == 0) ((volatile unsigned*)g_flags)[bid] = epoch;
        if (tid < 16) {
            volatile unsigned* vf = (volatile unsigned*)g_flags + bi * 16;
            while (vf[tid] < epoch) {}
        }
        __threadfence();
        __syncthreads();
    }
}

// ---------------------------------------------------------------------------
extern "C" void kernel_launch(void* const* d_in, const int* in_sizes, int n_in,
                              void* d_out, int out_size)
{
    (void)in_sizes; (void)n_in; (void)out_size;
    const float* x    = (const float*)d_in[0];  // [T,B,I]
    const float* h0   = (const float*)d_in[1];  // [B,N]
    const float* W_in = (const float*)d_in[2];  // [N,I]
    const float* b_in = (const float*)d_in[3];  // [N]
    const float* W_hh = (const float*)d_in[4];  // [N,N]
    float* out = (float*)d_out;                 // [T,B,N] then [B,N]

    // 1) xproj = x @ W_in^T + b_in  -> written straight into out[0 : T*B*N]
    {
        dim3 grid(NDIM / 128, (T_STEPS * BATCH) / 128);
        gemm_in_kernel<<<grid, 256>>>(x, W_in, b_in, out);
    }

    // 2) persistent scan over 1000 steps (in-place on out slices)
    {
        size_t smem = (size_t)SMEM_FLOATS * sizeof(float); // ~164 KB
        cudaFuncSetAttribute(ctrnn_scan_kernel,
                             cudaFuncAttributeMaxDynamicSharedMemorySize,
                             (int)smem);
        dim3 grid(16, 8);  // 128 blocks, co-resident on 148 SMs
        ctrnn_scan_kernel<<<grid, 256, smem>>>(h0, W_hh, out);
    }

    // 3) hidden = out[T-1] duplicated after the output block
    {
        size_t slice = (size_t)BATCH * NDIM * sizeof(float);
        cudaMemcpyAsync((char*)d_out + (size_t)T_STEPS * BATCH * NDIM * sizeof(float),
                        (char*)d_out + (size_t)(T_STEPS - 1) * BATCH * NDIM * sizeof(float),
                        slice, cudaMemcpyDeviceToDevice, 0);
    }
}

// round 7
// speedup vs baseline: 1.2507x; 1.2507x over previous
#include <cuda_runtime.h>
#include <math.h>

#define T_STEPS 1000
#define BATCH   256
#define IDIM    128
#define NDIM    512
#define ALPHA   0.2f
#define NB      128    // persistent scan blocks (16 n-tiles x 8 b-tiles)

#define NGROUPS 8       // one warp per k-group, each covers 64 k
#define KSLICE  64
#define RED_STRIDE 36   // 32 + 4 pad

// Shared memory layout (floats):
//   Wl  [512][32]            @ 0       (64 KB)  W_hh slice, resident all steps
//   Hs  [8][32 rows][64]     @ 16384   (64 KB)  per-group hprev, XOR-swizzled
//   red [8][32][RED_STRIDE]  @ 32768   (36 KB)  per-group partial sums
#define SMEM_WL   0
#define SMEM_HS   16384
#define SMEM_RED  32768
#define SMEM_FLOATS (SMEM_RED + NGROUPS * 32 * RED_STRIDE)   // 41984

// ---------------------------------------------------------------------------
// Grid barrier flags (persistent; epoch derived from flag state => replay-safe)
// ---------------------------------------------------------------------------
__device__ unsigned g_flags[NB];

// ---------------------------------------------------------------------------
// Input projection GEMM:  C[M,N] = X[M,K] * W[N,K]^T + b
// M = T*B = 256000, K = 128, N = 512.  Tile 128x128, BK=16, 256 thr, 8x8 micro.
// ---------------------------------------------------------------------------
__global__ __launch_bounds__(256) void gemm_in_kernel(
    const float* __restrict__ X, const float* __restrict__ W,
    const float* __restrict__ bias, float* __restrict__ C)
{
    const int BK = 16;
    __shared__ float As[BK][128 + 4];
    __shared__ float Bs[BK][128 + 4];

    const int tid = threadIdx.x;
    const int tx = tid & 15;   // n group (8 cols each)
    const int ty = tid >> 4;   // m group (8 rows each)
    const int mBase = blockIdx.y * 128;
    const int nBase = blockIdx.x * 128;
    const float* Xblk = X + (size_t)mBase * IDIM;
    const float* Wblk = W + (size_t)nBase * IDIM;

    float acc[8][8];
#pragma unroll
    for (int i = 0; i < 8; i++)
#pragma unroll
        for (int j = 0; j < 8; j++) acc[i][j] = 0.f;

    for (int kc = 0; kc < IDIM; kc += BK) {
#pragma unroll
        for (int r = 0; r < 2; r++) {
            int f = tid + r * 256;          // [0,512) float4 slots
            int m = f >> 2;                 // row within tile
            int q = f & 3;                  // which float4 of the 16-wide k chunk
            float4 va = *(const float4*)(Xblk + (size_t)m * IDIM + kc + q * 4);
            As[q * 4 + 0][m] = va.x; As[q * 4 + 1][m] = va.y;
            As[q * 4 + 2][m] = va.z; As[q * 4 + 3][m] = va.w;
            float4 vb = *(const float4*)(Wblk + (size_t)m * IDIM + kc + q * 4);
            Bs[q * 4 + 0][m] = vb.x; Bs[q * 4 + 1][m] = vb.y;
            Bs[q * 4 + 2][m] = vb.z; Bs[q * 4 + 3][m] = vb.w;
        }
        __syncthreads();
#pragma unroll
        for (int k = 0; k < BK; k++) {
            float a[8], b[8];
            *(float4*)&a[0] = *(const float4*)&As[k][ty * 8];
            *(float4*)&a[4] = *(const float4*)&As[k][ty * 8 + 4];
            *(float4*)&b[0] = *(const float4*)&Bs[k][tx * 8];
            *(float4*)&b[4] = *(const float4*)&Bs[k][tx * 8 + 4];
#pragma unroll
            for (int i = 0; i < 8; i++)
#pragma unroll
                for (int j = 0; j < 8; j++)
                    acc[i][j] = fmaf(a[i], b[j], acc[i][j]);
        }
        __syncthreads();
    }

#pragma unroll
    for (int i = 0; i < 8; i++) {
        int m = mBase + ty * 8 + i;
        float* crow = C + (size_t)m * NDIM + nBase + tx * 8;
#pragma unroll
        for (int j = 0; j < 8; j++)
            crow[j] = acc[i][j] + bias[nBase + tx * 8 + j];
    }
}

// ---------------------------------------------------------------------------
// Persistent recurrent scan kernel. 128 blocks x 256 threads (8 warps).
//   Block (bi, ni): output tile rows [bi*32,+32) x cols [ni*32,+32).
//   Warp g covers k in [g*64, g*64+64); lane micro-tile 8b x 4n, acc[8][4].
//   Hs swizzle: phys_f4(row, kq) = row*16 + (kq ^ (row>>3))  -> the 4 rows
//   {8ty+i} touched by one a-load land in distinct bank quads.
// ---------------------------------------------------------------------------
extern __shared__ float s_mem[];

__global__ __launch_bounds__(256, 1) void ctrnn_scan_kernel(
    const float* __restrict__ h0,
    const float* __restrict__ W_hh,
    float* __restrict__ out)
{
    float* Wl = s_mem + SMEM_WL;

    const int tid  = threadIdx.x;
    const int g    = tid >> 5;      // warp / k-group 0..7
    const int lane = tid & 31;
    const int tx   = lane & 7;      // n micro (4 cols)
    const int ty   = lane >> 3;     // b micro (8 rows), 0..3
    const int kOff = g * KSLICE;

    const int ni = blockIdx.x;      // 0..15
    const int bi = blockIdx.y;      // 0..7
    const int bid = bi * 16 + ni;
    const int nBase = ni * 32;
    const int bBase = bi * 32;

    float* HsG  = s_mem + SMEM_HS  + g * (32 * 64);
    float* redG = s_mem + SMEM_RED + g * (32 * RED_STRIDE);

    // epilogue mapping: one float4 of the 32x32 tile per thread
    const int eb = tid >> 3;
    const int en = tid & 7;

    // Load W_hh[nBase..+32)[0..512) transposed into Wl[k][n_local]. Once.
    for (int f = tid; f < 32 * (NDIM / 4); f += 256) {
        int n = f >> 7;          // local n row
        int q = f & 127;         // float4 along k
        float4 v = *(const float4*)(W_hh + (size_t)(nBase + n) * NDIM + q * 4);
        Wl[(q * 4 + 0) * 32 + n] = v.x; Wl[(q * 4 + 1) * 32 + n] = v.y;
        Wl[(q * 4 + 2) * 32 + n] = v.z; Wl[(q * 4 + 3) * 32 + n] = v.w;
    }

    // Replay-safe epoch base: all flags equal at kernel entry.
    unsigned base = ((volatile unsigned*)g_flags)[bid];
    __syncthreads();

    for (int t = 0; t < T_STEPS; t++) {
        const float* hprev = (t == 0) ? h0 : out + (size_t)(t - 1) * BATCH * NDIM;
        float* hcur = out + (size_t)t * BATCH * NDIM;

        // Epilogue operands prefetch (valid after previous barrier).
        const size_t eoff = (size_t)(bBase + eb) * NDIM + nBase + en * 4;
        float4 xp4 = *(const float4*)(hcur + eoff);
        float4 hp4 = __ldcg((const float4*)(hprev + eoff));

        // Stage this warp's 64-k slice of the 32-row hprev tile, swizzled.
#pragma unroll
        for (int r = 0; r < 16; r++) {
            int f = lane + r * 32;
            int kq = f & 15;         // float4 within 64-wide slice
            int bl = f >> 4;         // local b row
            float4 v = __ldcg((const float4*)(hprev +
                          (size_t)(bBase + bl) * NDIM + kOff + kq * 4));
            int phys = bl * 16 + (kq ^ (bl >> 3));
            *(float4*)(HsG + phys * 4) = v;
        }
        __syncwarp();

        float acc[8][4];
#pragma unroll
        for (int i = 0; i < 8; i++)
#pragma unroll
            for (int j = 0; j < 4; j++) acc[i][j] = 0.f;

        const float* aBase = HsG + (8 * ty) * 64;
        const float* wBase = Wl + (size_t)kOff * 32 + tx * 4;

#pragma unroll 2
        for (int kq = 0; kq < 16; kq++) {
            const int sw = (kq ^ ty) * 4;
            float a[8][4];
#pragma unroll
            for (int i = 0; i < 8; i++)
                *(float4*)a[i] = *(const float4*)(aBase + i * 64 + sw);
#pragma unroll
            for (int kk = 0; kk < 4; kk++) {
                float w[4];
                *(float4*)w = *(const float4*)(wBase + (kq * 4 + kk) * 32);
#pragma unroll
                for (int i = 0; i < 8; i++) {
#pragma unroll
                    for (int j = 0; j < 4; j++)
                        acc[i][j] = fmaf(a[i][kk], w[j], acc[i][j]);
                }
            }
        }

        // Write partials; reduce + epilogue with all 256 threads.
#pragma unroll
        for (int i = 0; i < 8; i++) {
            *(float4*)(redG + (8 * ty + i) * RED_STRIDE + tx * 4) =
                make_float4(acc[i][0], acc[i][1], acc[i][2], acc[i][3]);
        }
        __syncthreads();

        {
            float4 s = make_float4(0.f, 0.f, 0.f, 0.f);
#pragma unroll
            for (int gg = 0; gg < NGROUPS; gg++) {
                float4 p = *(const float4*)(s_mem + SMEM_RED
                            + gg * (32 * RED_STRIDE) + eb * RED_STRIDE + en * 4);
                s.x += p.x; s.y += p.y; s.z += p.z; s.w += p.w;
            }
            float4 o;
            o.x = hp4.x * (1.f - ALPHA) + ALPHA * tanhf(xp4.x + s.x);
            o.y = hp4.y * (1.f - ALPHA) + ALPHA * tanhf(xp4.y + s.y);
            o.z = hp4.z * (1.f - ALPHA) + ALPHA * tanhf(xp4.z + s.z);
            o.w = hp4.w * (1.f - ALPHA) + ALPHA * tanhf(xp4.w + s.w);
            *(float4*)(hcur + eoff) = o;
        }

        // ---- barrier among the 16 blocks sharing bi (release/acquire) ----
        unsigned epoch = base + (unsigned)t + 1u;
        __syncthreads();   // all epilogue STGs issued before tid0's release
        if (tid == 0) {
            asm volatile("st.release.gpu.global.u32 [%0], %1;"
                         :: "l"(&g_flags[bid]), "r"(epoch) : "memory");
        }
        if (tid < 16) {
            unsigned v;
            do {
                asm volatile("ld.acquire.gpu.global.u32 %0, [%1];"
                             : "=r"(v) : "l"(&g_flags[bi * 16 + tid]) : "memory");
            } while (v < epoch);
        }
        __syncthreads();
    }
}

// ---------------------------------------------------------------------------
extern "C" void kernel_launch(void* const* d_in, const int* in_sizes, int n_in,
                              void* d_out, int out_size)
{
    (void)in_sizes; (void)n_in; (void)out_size;
    const float* x    = (const float*)d_in[0];  // [T,B,I]
    const float* h0   = (const float*)d_in[1];  // [B,N]
    const float* W_in = (const float*)d_in[2];  // [N,I]
    const float* b_in = (const float*)d_in[3];  // [N]
    const float* W_hh = (const float*)d_in[4];  // [N,N]
    float* out = (float*)d_out;                 // [T,B,N] then [B,N]

    // 1) xproj = x @ W_in^T + b_in  -> written straight into out[0 : T*B*N]
    {
        dim3 grid(NDIM / 128, (T_STEPS * BATCH) / 128);
        gemm_in_kernel<<<grid, 256>>>(x, W_in, b_in, out);
    }

    // 2) persistent scan over 1000 steps (in-place on out slices)
    {
        size_t smem = (size_t)SMEM_FLOATS * sizeof(float); // ~164 KB
        cudaFuncSetAttribute(ctrnn_scan_kernel,
                             cudaFuncAttributeMaxDynamicSharedMemorySize,
                             (int)smem);
        dim3 grid(16, 8);  // 128 blocks, co-resident on 148 SMs
        ctrnn_scan_kernel<<<grid, 256, smem>>>(h0, W_hh, out);
    }

    // 3) hidden = out[T-1] duplicated after the output block
    {
        size_t slice = (size_t)BATCH * NDIM * sizeof(float);
        cudaMemcpyAsync((char*)d_out + (size_t)T_STEPS * BATCH * NDIM * sizeof(float),
                        (char*)d_out + (size_t)(T_STEPS - 1) * BATCH * NDIM * sizeof(float),
                        slice, cudaMemcpyDeviceToDevice, 0);
    }
}